// round 14
// baseline (speedup 1.0000x reference)
#include <cuda_runtime.h>
#include <cuda_bf16.h>
#include <stdint.h>
#include <math.h>

#define S_LEN 256
#define BATCH 64
#define VOCAB 10000
#define EDIM  512
#define HDIM  1024

typedef unsigned long long u64;

// ---------------- warp-level mma helpers --------------------------------
__device__ __forceinline__ uint32_t s2u(const void* p) {
    uint32_t a;
    asm("{ .reg .u64 t; cvta.to.shared.u64 t, %1; cvt.u32.u64 %0, t; }" : "=r"(a) : "l"(p));
    return a;
}
__device__ __forceinline__ void ldsm4(uint32_t* r, uint32_t addr) {
    asm volatile("ldmatrix.sync.aligned.m8n8.x4.shared.b16 {%0,%1,%2,%3}, [%4];"
        : "=r"(r[0]), "=r"(r[1]), "=r"(r[2]), "=r"(r[3]) : "r"(addr));
}
__device__ __forceinline__ void ldsm2(uint32_t* r, uint32_t addr) {
    asm volatile("ldmatrix.sync.aligned.m8n8.x2.shared.b16 {%0,%1}, [%2];"
        : "=r"(r[0]), "=r"(r[1]) : "r"(addr));
}
__device__ __forceinline__ void mma16816(float* d, const uint32_t* a, const uint32_t* b) {
    asm volatile(
        "mma.sync.aligned.m16n8k16.row.col.f32.bf16.bf16.f32 "
        "{%0,%1,%2,%3},{%4,%5,%6,%7},{%8,%9},{%0,%1,%2,%3};"
        : "+f"(d[0]), "+f"(d[1]), "+f"(d[2]), "+f"(d[3])
        : "r"(a[0]), "r"(a[1]), "r"(a[2]), "r"(a[3]), "r"(b[0]), "r"(b[1]));
}

// ---------------- scratch (static device memory) ------------------------
__device__ float g_bias[6 * 1024];
__device__ float g_xpre[(size_t)16384 * 3072];
__device__ float g_cat[64 * 2048];
__device__ float g_z[64 * 1024];
__device__ float g_xh1[64 * 1024];
__device__ float g_part[2359296];
__device__ int   g_cnt1[32] = {};
__device__ int   g_fix[32] = {};
__device__ int   g_root = 0;
__device__ int   g_gen = 0;
// bf16 hi/lo recurrent weights, [n][k] layout
__device__ __nv_bfloat16 g_W0An_H[(size_t)2048 * 1024], g_W0An_L[(size_t)2048 * 1024];
__device__ __nv_bfloat16 g_W0Bn_H[(size_t)1024 * 1024], g_W0Bn_L[(size_t)1024 * 1024];
__device__ __nv_bfloat16 g_W1An_H[(size_t)3072 * 2048], g_W1An_L[(size_t)3072 * 2048];
__device__ __nv_bfloat16 g_W1Bn_H[(size_t)1024 * 1024], g_W1Bn_L[(size_t)1024 * 1024];
// x-side weights [n][k] + embedding split
__device__ __nv_bfloat16 g_W0Xn_H[(size_t)3072 * 512], g_W0Xn_L[(size_t)3072 * 512];
__device__ __nv_bfloat16 g_EmbH[(size_t)10000 * 512], g_EmbL[(size_t)10000 * 512];
// bf16 hi/lo states
__device__ __nv_bfloat16 g_catH[64 * 2048], g_catL[64 * 2048];
__device__ __nv_bfloat16 g_rhH[64 * 1024], g_rhL[64 * 1024];
// bf16 split logits operands
__device__ __nv_bfloat16 g_topH[(size_t)16384 * 1024];
__device__ __nv_bfloat16 g_topL[(size_t)16384 * 1024];
__device__ __nv_bfloat16 g_WoH[(size_t)10000 * 1024];
__device__ __nv_bfloat16 g_WoL[(size_t)10000 * 1024];

// ---------------- two-level grid barrier -------------------------------
__device__ __forceinline__ void grid_bar(int &gen) {
    __syncthreads();
    if (threadIdx.x == 0) {
        __threadfence();
        int g = blockIdx.x >> 3;
        int ngrp = ((int)gridDim.x + 7) >> 3;
        int gsz = min(8, (int)gridDim.x - (g << 3));
        if (atomicAdd(&g_cnt1[g], 1) == gsz - 1) {
            atomicExch(&g_cnt1[g], 0);
            if (atomicAdd(&g_root, 1) == ngrp - 1) {
                atomicExch(&g_root, 0);
                __threadfence();
                atomicAdd(&g_gen, 1);
            }
        }
        volatile int* vg = &g_gen;
        while (*vg - gen <= 0) { }
        __threadfence();
    }
    gen++;
    __syncthreads();
}

// ---------------- prep: bias + initial state ---------------------------
__global__ void k_prep(const float* __restrict__ hidden,
                       const float* __restrict__ br0, const float* __restrict__ bz0,
                       const float* __restrict__ bh0,
                       const float* __restrict__ br1, const float* __restrict__ bz1,
                       const float* __restrict__ bh1) {
    int i = blockIdx.x * blockDim.x + threadIdx.x;
    if (i < 1024) {
        g_bias[i]        = br0[i]; g_bias[1024 + i] = bz0[i]; g_bias[2048 + i] = bh0[i];
        g_bias[3072 + i] = br1[i]; g_bias[4096 + i] = bz1[i]; g_bias[5120 + i] = bh1[i];
    }
    if (i < 64 * 2048) {
        int b = i >> 11, j = i & 2047;
        float v = (j < 1024) ? hidden[b * 1024 + j]
                             : hidden[65536 + b * 1024 + (j - 1024)];
        g_cat[i] = v;
        __nv_bfloat16 hi = __float2bfloat16(v);
        g_catH[i] = hi;
        g_catL[i] = __float2bfloat16(v - __bfloat162float(hi));
    }
}

// ---------------- weight repack: [k][n] -> [n][k] bf16 hi/lo -----------
__global__ __launch_bounds__(256) void k_wprep(
    const float* __restrict__ Wr0, const float* __restrict__ Wz0, const float* __restrict__ Wh0,
    const float* __restrict__ Wr1, const float* __restrict__ Wz1, const float* __restrict__ Wh1) {
    __shared__ float t[32][33];
    const int which = blockIdx.z;
    const int Ns[5] = {2048, 1024, 3072, 1024, 3072};
    const int Ks[5] = {1024, 1024, 2048, 1024, 512};
    const int N = Ns[which], K = Ks[which];
    int n0 = blockIdx.x * 32, k0 = blockIdx.y * 32;
    if (n0 >= N || k0 >= K) return;
    int tx = threadIdx.x & 31, ty = threadIdx.x >> 5;
#pragma unroll
    for (int j = ty; j < 32; j += 8) {
        int k = k0 + j, n = n0 + tx;
        float v;
        if (which == 0)      v = (n < 1024) ? Wr0[(512 + k) * 1024 + n] : Wz0[(512 + k) * 1024 + n - 1024];
        else if (which == 1) v = Wh0[(512 + k) * 1024 + n];
        else if (which == 2) v = (n < 1024) ? Wr1[k * 1024 + n]
                               : (n < 2048) ? Wz1[k * 1024 + n - 1024]
                               : ((k < 1024) ? Wh1[k * 1024 + (n - 2048)] : 0.f);
        else if (which == 3) v = Wh1[(1024 + k) * 1024 + n];
        else                 v = (n < 1024) ? Wr0[k * 1024 + n]
                               : (n < 2048) ? Wz0[k * 1024 + n - 1024]
                               : Wh0[k * 1024 + n - 2048];
        t[j][tx] = v;
    }
    __syncthreads();
    __nv_bfloat16 *dH, *dL;
    if (which == 0)      { dH = g_W0An_H; dL = g_W0An_L; }
    else if (which == 1) { dH = g_W0Bn_H; dL = g_W0Bn_L; }
    else if (which == 2) { dH = g_W1An_H; dL = g_W1An_L; }
    else if (which == 3) { dH = g_W1Bn_H; dL = g_W1Bn_L; }
    else                 { dH = g_W0Xn_H; dL = g_W0Xn_L; }
#pragma unroll
    for (int j = ty; j < 32; j += 8) {
        int n = n0 + j, k = k0 + tx;
        float v = t[tx][j];
        __nv_bfloat16 hi = __float2bfloat16(v);
        dH[(size_t)n * K + k] = hi;
        dL[(size_t)n * K + k] = __float2bfloat16(v - __bfloat162float(hi));
    }
}

// ---------------- Emb split --------------------------------------------
__global__ __launch_bounds__(256) void k_esplit(const float* __restrict__ Emb) {
    size_t i = (size_t)blockIdx.x * 256 + threadIdx.x;
    if (i < (size_t)10000 * 512) {
        float v = Emb[i];
        __nv_bfloat16 hi = __float2bfloat16(v);
        g_EmbH[i] = hi;
        g_EmbL[i] = __float2bfloat16(v - __bfloat162float(hi));
    }
}

// ---------------- Wout split+transpose ---------------------------------
__global__ __launch_bounds__(256) void k_wsplit(const float* __restrict__ Wout) {
    __shared__ float t[32][33];
    int tx = threadIdx.x & 31, ty = threadIdx.x >> 5;
    int n0 = blockIdx.x * 32, k0 = blockIdx.y * 32;
#pragma unroll
    for (int j = ty; j < 32; j += 8) {
        float v = 0.f;
        if (n0 + tx < VOCAB) v = Wout[(size_t)(k0 + j) * VOCAB + n0 + tx];
        t[j][tx] = v;
    }
    __syncthreads();
#pragma unroll
    for (int j = ty; j < 32; j += 8) {
        int n = n0 + j;
        if (n < VOCAB) {
            float v = t[tx][j];
            __nv_bfloat16 hi = __float2bfloat16(v);
            g_WoH[(size_t)n * 1024 + k0 + tx] = hi;
            g_WoL[(size_t)n * 1024 + k0 + tx] = __float2bfloat16(v - __bfloat162float(hi));
        }
    }
}

// ---------------- embed GEMM via mma.sync ------------------------------
__global__ __launch_bounds__(256) void k_embed_mma(const int* __restrict__ inputs) {
    __shared__ __align__(16) __nv_bfloat16 sAH[128 * 32];
    __shared__ __align__(16) __nv_bfloat16 sAL[128 * 32];
    __shared__ __align__(16) __nv_bfloat16 sBH[128 * 32];
    __shared__ __align__(16) __nv_bfloat16 sBL[128 * 32];
    __shared__ int stok[128];
    const int tid = threadIdx.x, wid = tid >> 5, lane = tid & 31;
    const int m0 = blockIdx.y * 128, n0 = blockIdx.x * 128;
    const int wm = (wid & 1) * 64, wn = (wid >> 1) * 32;
    const uint32_t bAH = s2u(sAH), bAL = s2u(sAL), bBH = s2u(sBH), bBL = s2u(sBL);
    if (tid < 128) stok[tid] = inputs[m0 + tid];
    __syncthreads();

    float acc[4][4][4];
#pragma unroll
    for (int i = 0; i < 4; i++)
#pragma unroll
        for (int j = 0; j < 4; j++)
#pragma unroll
            for (int q = 0; q < 4; q++) acc[i][j][q] = 0.f;

    for (int kc = 0; kc < 16; kc++) {
        const int k0 = kc * 32;
#pragma unroll
        for (int h = 0; h < 2; h++) {
            int row = (tid >> 2) + h * 64;
            int g = tid & 3;
            uint32_t off = row * 64 + ((g ^ ((row >> 1) & 3)) << 4);
            size_t goA = (size_t)stok[row] * 512 + k0 + g * 8;
            *(uint4*)((char*)sAH + off) = *(const uint4*)&g_EmbH[goA];
            *(uint4*)((char*)sAL + off) = *(const uint4*)&g_EmbL[goA];
            size_t goB = (size_t)(n0 + row) * 512 + k0 + g * 8;
            *(uint4*)((char*)sBH + off) = *(const uint4*)&g_W0Xn_H[goB];
            *(uint4*)((char*)sBL + off) = *(const uint4*)&g_W0Xn_L[goB];
        }
        __syncthreads();
#pragma unroll
        for (int kb = 0; kb < 32; kb += 16) {
            uint32_t aH[4][4], aL[4][4], bH[4][2], bL[4][2];
            int ar = wm + (lane & 15);
            int ag = (kb >> 3) + (lane >> 4);
#pragma unroll
            for (int mf = 0; mf < 4; mf++) {
                int m = ar + mf * 16;
                uint32_t off = m * 64 + ((ag ^ ((m >> 1) & 3)) << 4);
                ldsm4(aH[mf], bAH + off);
                ldsm4(aL[mf], bAL + off);
            }
            int br = wn + (lane & 7);
            int bg = (kb >> 3) + ((lane >> 3) & 1);
#pragma unroll
            for (int nf = 0; nf < 4; nf++) {
                int n = br + nf * 8;
                uint32_t off = n * 64 + ((bg ^ ((n >> 1) & 3)) << 4);
                ldsm2(bH[nf], bBH + off);
                ldsm2(bL[nf], bBL + off);
            }
#pragma unroll
            for (int mf = 0; mf < 4; mf++)
#pragma unroll
                for (int nf = 0; nf < 4; nf++) {
                    mma16816(acc[mf][nf], aH[mf], bH[nf]);
                    mma16816(acc[mf][nf], aH[mf], bL[nf]);
                    mma16816(acc[mf][nf], aL[mf], bH[nf]);
                }
        }
        __syncthreads();
    }
    int r0 = m0 + wm + (lane >> 2);
    int c0 = n0 + wn + (lane & 3) * 2;
#pragma unroll
    for (int mf = 0; mf < 4; mf++)
#pragma unroll
        for (int nf = 0; nf < 4; nf++) {
            int r = r0 + mf * 16, c = c0 + nf * 8;
            *(float2*)&g_xpre[(size_t)r * 3072 + c] = make_float2(acc[mf][nf][0], acc[mf][nf][1]);
            *(float2*)&g_xpre[(size_t)(r + 8) * 3072 + c] = make_float2(acc[mf][nf][2], acc[mf][nf][3]);
        }
}

// ---------------- pipelined split-K GEMM phase (recurrence) ------------
// dynamic smem: A buffers [iters<=11][64 rows][64B] hi at 0, lo at 45056;
// B double buffer at 90112: {BH0,BL0,BH1,BL1} each 8192. total 122880.
#define SMA_L 45056
#define SMB_0 90112
#define REC_SMEM 122880

__device__ __forceinline__ void phase_mma(char* sm,
    const __nv_bfloat16* __restrict__ AH, const __nv_bfloat16* __restrict__ AL, int lda,
    const __nv_bfloat16* __restrict__ BH, const __nv_bfloat16* __restrict__ BL, int ldbk,
    int N, int ntile, int sp, int kbeg, int kend) {
    const int tid = threadIdx.x, wid = tid >> 5, lane = tid & 31;
    const int n0 = ntile * 128;
    const int wm = (wid & 1) * 32, wn = (wid >> 1) * 32;
    const uint32_t sbase = s2u(sm);
    const int iters = (kend - kbeg) >> 5;
    float acc[2][4][4];
#pragma unroll
    for (int i = 0; i < 2; i++)
#pragma unroll
        for (int j = 0; j < 4; j++)
#pragma unroll
            for (int q = 0; q < 4; q++) acc[i][j][q] = 0.f;

    // A slices upfront (high MLP)
    {
        int row = tid >> 2, g = tid & 3;
        uint32_t off = row * 64 + ((g ^ ((row >> 1) & 3)) << 4);
        for (int it = 0; it < iters; it++) {
            size_t go = (size_t)row * lda + kbeg + it * 32 + g * 8;
            *(uint4*)(sm + it * 4096 + off)         = __ldcg((const uint4*)(AH + go));
            *(uint4*)(sm + SMA_L + it * 4096 + off) = __ldcg((const uint4*)(AL + go));
        }
    }
    // B prefetch iter 0 into registers
    uint4 rbh[2], rbl[2];
    int brow[2]; uint32_t bsoff[2]; int bg4[2];
#pragma unroll
    for (int q = 0; q < 2; q++) {
        int s = tid * 2 + q;
        int row = s >> 2, g = s & 3;
        brow[q] = row; bg4[q] = g;
        bsoff[q] = row * 64 + ((g ^ ((row >> 1) & 3)) << 4);
        size_t go = (size_t)(n0 + row) * ldbk + kbeg + g * 8;
        rbh[q] = *(const uint4*)(BH + go);
        rbl[q] = *(const uint4*)(BL + go);
    }
    __syncthreads();
    for (int it = 0; it < iters; it++) {
        uint32_t bb = SMB_0 + (it & 1) * 16384;
#pragma unroll
        for (int q = 0; q < 2; q++) {
            *(uint4*)(sm + bb + bsoff[q])        = rbh[q];
            *(uint4*)(sm + bb + 8192 + bsoff[q]) = rbl[q];
        }
        __syncthreads();
        if (it + 1 < iters) {
#pragma unroll
            for (int q = 0; q < 2; q++) {
                size_t go = (size_t)(n0 + brow[q]) * ldbk + kbeg + (it + 1) * 32 + bg4[q] * 8;
                rbh[q] = *(const uint4*)(BH + go);
                rbl[q] = *(const uint4*)(BL + go);
            }
        }
        uint32_t aH_b = sbase + it * 4096;
        uint32_t aL_b = sbase + SMA_L + it * 4096;
        uint32_t bH_b = sbase + bb;
        uint32_t bL_b = sbase + bb + 8192;
#pragma unroll
        for (int kb = 0; kb < 32; kb += 16) {
            uint32_t aH[2][4], aL[2][4], bH[4][2], bL[4][2];
            int ag = (kb >> 3) + (lane >> 4);
#pragma unroll
            for (int mf = 0; mf < 2; mf++) {
                int m = wm + (lane & 15) + mf * 16;
                uint32_t off = m * 64 + ((ag ^ ((m >> 1) & 3)) << 4);
                ldsm4(aH[mf], aH_b + off);
                ldsm4(aL[mf], aL_b + off);
            }
            int bg = (kb >> 3) + ((lane >> 3) & 1);
#pragma unroll
            for (int nf = 0; nf < 4; nf++) {
                int n = wn + (lane & 7) + nf * 8;
                uint32_t off = n * 64 + ((bg ^ ((n >> 1) & 3)) << 4);
                ldsm2(bH[nf], bH_b + off);
                ldsm2(bL[nf], bL_b + off);
            }
#pragma unroll
            for (int mf = 0; mf < 2; mf++)
#pragma unroll
                for (int nf = 0; nf < 4; nf++) {
                    mma16816(acc[mf][nf], aH[mf], bH[nf]);
                    mma16816(acc[mf][nf], aH[mf], bL[nf]);
                    mma16816(acc[mf][nf], aL[mf], bH[nf]);
                }
        }
        __syncthreads();
    }
    float* part = g_part + (size_t)sp * 64 * N;
    int r0 = wm + (lane >> 2), c0 = wn + (lane & 3) * 2;
#pragma unroll
    for (int mf = 0; mf < 2; mf++)
#pragma unroll
        for (int nf = 0; nf < 4; nf++) {
            int r = r0 + mf * 16, c = n0 + c0 + nf * 8;
            *(float2*)&part[(size_t)r * N + c]       = make_float2(acc[mf][nf][0], acc[mf][nf][1]);
            *(float2*)&part[(size_t)(r + 8) * N + c] = make_float2(acc[mf][nf][2], acc[mf][nf][3]);
        }
}

// last-arriving split-CTA becomes the fixer for its ntile
__device__ __forceinline__ int arrive_last(int nt, int sp) {
    __shared__ int s_last;
    __threadfence();
    __syncthreads();
    if (threadIdx.x == 0)
        s_last = (atomicAdd(&g_fix[nt], 1) == sp - 1) ? 1 : 0;
    __syncthreads();
    if (s_last) __threadfence();
    return s_last;
}

__device__ __forceinline__ float sigm(float x) { return 1.f / (1.f + expf(-x)); }
__device__ __forceinline__ void split4(const float* v, __nv_bfloat16* H, __nv_bfloat16* L, int idx) {
    __nv_bfloat162 h0, h1, l0, l1;
    __nv_bfloat16 a = __float2bfloat16(v[0]), b = __float2bfloat16(v[1]);
    __nv_bfloat16 c = __float2bfloat16(v[2]), d = __float2bfloat16(v[3]);
    h0.x = a; h0.y = b; h1.x = c; h1.y = d;
    l0.x = __float2bfloat16(v[0] - __bfloat162float(a));
    l0.y = __float2bfloat16(v[1] - __bfloat162float(b));
    l1.x = __float2bfloat16(v[2] - __bfloat162float(c));
    l1.y = __float2bfloat16(v[3] - __bfloat162float(d));
    *(__nv_bfloat162*)&H[idx] = h0; *(__nv_bfloat162*)&H[idx + 2] = h1;
    *(__nv_bfloat162*)&L[idx] = l0; *(__nv_bfloat162*)&L[idx + 2] = l1;
}

// ---------------- persistent recurrent kernel --------------------------
__global__ __launch_bounds__(256) void k_rec_persist() {
    extern __shared__ __align__(16) char dsm[];
    const int cta = blockIdx.x, tid = threadIdx.x;
    int gen = *(volatile int*)&g_gen;

    for (int s = 0; s < S_LEN; s++) {
        const int sb = s * BATCH;
        // ---- G1+fix1: h0 @ W0A  (16 nt x 8 sp, K128) ----
        if (cta < 128) {
            int nt = cta & 15, sp = cta >> 4;
            phase_mma(dsm, g_catH, g_catL, 2048, g_W0An_H, g_W0An_L, 1024,
                      2048, nt, sp, sp * 128, sp * 128 + 128);
            if (arrive_last(nt, 8)) {
                int n0 = nt * 128;
                for (int idx = tid; idx < 2048; idx += 256) {
                    int r = idx >> 5, n = n0 + (idx & 31) * 4;
                    int e = r * 2048 + n;
                    float4 s4 = make_float4(0.f, 0.f, 0.f, 0.f);
#pragma unroll
                    for (int p = 0; p < 8; p++) {
                        float4 v = __ldcg((const float4*)&g_part[p * 131072 + e]);
                        s4.x += v.x; s4.y += v.y; s4.z += v.z; s4.w += v.w;
                    }
                    float4 xp = *(const float4*)&g_xpre[(size_t)(sb + r) * 3072 + n];
                    float4 bi = *(const float4*)&g_bias[n];
                    float pre[4] = { s4.x + xp.x + bi.x, s4.y + xp.y + bi.y,
                                     s4.z + xp.z + bi.z, s4.w + xp.w + bi.w };
                    if (n < 1024) {
                        float4 cc = __ldcg((const float4*)&g_cat[r * 2048 + n]);
                        float rh[4] = { sigm(pre[0]) * cc.x, sigm(pre[1]) * cc.y,
                                        sigm(pre[2]) * cc.z, sigm(pre[3]) * cc.w };
                        split4(rh, g_rhH, g_rhL, r * 1024 + n);
                    } else {
                        int j = n - 1024;
                        *(float4*)&g_z[r * 1024 + j] =
                            make_float4(sigm(pre[0]), sigm(pre[1]), sigm(pre[2]), sigm(pre[3]));
                    }
                }
                if (tid == 0) g_fix[nt] = 0;
            }
        }
        grid_bar(gen);
        // ---- G2+fix2: rh0 @ W0B  (8 nt x 8 sp, K128) ----
        if (cta < 64) {
            int nt = cta & 7, sp = cta >> 3;
            phase_mma(dsm, g_rhH, g_rhL, 1024, g_W0Bn_H, g_W0Bn_L, 1024,
                      1024, nt, sp, sp * 128, sp * 128 + 128);
            if (arrive_last(nt, 8)) {
                int n0 = nt * 128;
                for (int idx = tid; idx < 2048; idx += 256) {
                    int r = idx >> 5, n = n0 + (idx & 31) * 4;
                    int e = r * 1024 + n;
                    float4 s4 = make_float4(0.f, 0.f, 0.f, 0.f);
#pragma unroll
                    for (int p = 0; p < 8; p++) {
                        float4 v = __ldcg((const float4*)&g_part[p * 65536 + e]);
                        s4.x += v.x; s4.y += v.y; s4.z += v.z; s4.w += v.w;
                    }
                    float4 xp = *(const float4*)&g_xpre[(size_t)(sb + r) * 3072 + 2048 + n];
                    float4 bi = *(const float4*)&g_bias[2048 + n];
                    float4 z4 = __ldcg((const float4*)&g_z[e]);
                    float4 h4 = __ldcg((const float4*)&g_cat[r * 2048 + n]);
                    float hn[4];
                    hn[0] = (1.f - z4.x) * h4.x + z4.x * tanhf(s4.x + xp.x + bi.x);
                    hn[1] = (1.f - z4.y) * h4.y + z4.y * tanhf(s4.y + xp.y + bi.y);
                    hn[2] = (1.f - z4.z) * h4.z + z4.z * tanhf(s4.z + xp.z + bi.z);
                    hn[3] = (1.f - z4.w) * h4.w + z4.w * tanhf(s4.w + xp.w + bi.w);
                    *(float4*)&g_cat[r * 2048 + n] = make_float4(hn[0], hn[1], hn[2], hn[3]);
                    split4(hn, g_catH, g_catL, r * 2048 + n);
                }
                if (tid == 0) g_fix[nt] = 0;
            }
        }
        grid_bar(gen);
        // ---- G3+fix3: [h0new|h1] @ W1A  (24 nt x 6 sp, K352) ----
        if (cta < 144) {
            int nt = cta % 24, sp = cta / 24;
            int kb = sp * 352, ke = min(2048, kb + 352);
            phase_mma(dsm, g_catH, g_catL, 2048, g_W1An_H, g_W1An_L, 2048,
                      3072, nt, sp, kb, ke);
            if (arrive_last(nt, 6)) {
                int n0 = nt * 128;
                for (int idx = tid; idx < 2048; idx += 256) {
                    int r = idx >> 5, n = n0 + (idx & 31) * 4;
                    int e = r * 3072 + n;
                    float4 s4 = make_float4(0.f, 0.f, 0.f, 0.f);
#pragma unroll
                    for (int p = 0; p < 6; p++) {
                        float4 v = __ldcg((const float4*)&g_part[p * 196608 + e]);
                        s4.x += v.x; s4.y += v.y; s4.z += v.z; s4.w += v.w;
                    }
                    if (n < 1024) {
                        float4 bi = *(const float4*)&g_bias[3072 + n];
                        float4 cc = __ldcg((const float4*)&g_cat[r * 2048 + 1024 + n]);
                        float rh[4] = { sigm(s4.x + bi.x) * cc.x, sigm(s4.y + bi.y) * cc.y,
                                        sigm(s4.z + bi.z) * cc.z, sigm(s4.w + bi.w) * cc.w };
                        split4(rh, g_rhH, g_rhL, r * 1024 + n);
                    } else if (n < 2048) {
                        int j = n - 1024;
                        float4 bi = *(const float4*)&g_bias[4096 + j];
                        *(float4*)&g_z[r * 1024 + j] = make_float4(
                            sigm(s4.x + bi.x), sigm(s4.y + bi.y), sigm(s4.z + bi.z), sigm(s4.w + bi.w));
                    } else {
                        *(float4*)&g_xh1[r * 1024 + n - 2048] = s4;
                    }
                }
                if (tid == 0) g_fix[nt] = 0;
            }
        }
        grid_bar(gen);
        // ---- G4+fix4: rh1 @ W1B  (8 nt x 8 sp, K128) ----
        if (cta < 64) {
            int nt = cta & 7, sp = cta >> 3;
            phase_mma(dsm, g_rhH, g_rhL, 1024, g_W1Bn_H, g_W1Bn_L, 1024,
                      1024, nt, sp, sp * 128, sp * 128 + 128);
            if (arrive_last(nt, 8)) {
                int n0 = nt * 128;
                for (int idx = tid; idx < 2048; idx += 256) {
                    int r = idx >> 5, n = n0 + (idx & 31) * 4;
                    int e = r * 1024 + n;
                    float4 s4 = make_float4(0.f, 0.f, 0.f, 0.f);
#pragma unroll
                    for (int p = 0; p < 8; p++) {
                        float4 v = __ldcg((const float4*)&g_part[p * 65536 + e]);
                        s4.x += v.x; s4.y += v.y; s4.z += v.z; s4.w += v.w;
                    }
                    float4 xh = __ldcg((const float4*)&g_xh1[e]);
                    float4 bi = *(const float4*)&g_bias[5120 + n];
                    float4 z4 = __ldcg((const float4*)&g_z[e]);
                    float4 h4 = __ldcg((const float4*)&g_cat[r * 2048 + 1024 + n]);
                    float hn[4];
                    hn[0] = (1.f - z4.x) * h4.x + z4.x * tanhf(s4.x + xh.x + bi.x);
                    hn[1] = (1.f - z4.y) * h4.y + z4.y * tanhf(s4.y + xh.y + bi.y);
                    hn[2] = (1.f - z4.z) * h4.z + z4.z * tanhf(s4.z + xh.z + bi.z);
                    hn[3] = (1.f - z4.w) * h4.w + z4.w * tanhf(s4.w + xh.w + bi.w);
                    *(float4*)&g_cat[r * 2048 + 1024 + n] = make_float4(hn[0], hn[1], hn[2], hn[3]);
                    split4(hn, g_catH, g_catL, r * 2048 + 1024 + n);
                    split4(hn, g_topH, g_topL, (int)((size_t)(sb + r) * 1024 + n));
                }
                if (tid == 0) g_fix[nt] = 0;
            }
        }
        grid_bar(gen);
    }
}

// ---------------- logits GEMM via mma.sync (hi/lo, 3-pass) -------------
__global__ __launch_bounds__(256) void k_logits_mma(const float* __restrict__ bout,
                                                    float* __restrict__ out) {
    __shared__ __align__(16) __nv_bfloat16 sAH[128 * 32];
    __shared__ __align__(16) __nv_bfloat16 sAL[128 * 32];
    __shared__ __align__(16) __nv_bfloat16 sBH[128 * 32];
    __shared__ __align__(16) __nv_bfloat16 sBL[128 * 32];
    const int tid = threadIdx.x, wid = tid >> 5, lane = tid & 31;
    const int m0 = blockIdx.y * 128, n0 = blockIdx.x * 128;
    const int wm = (wid & 1) * 64, wn = (wid >> 1) * 32;
    const uint32_t bAH = s2u(sAH), bAL = s2u(sAL), bBH = s2u(sBH), bBL = s2u(sBL);

    float acc[4][4][4];
#pragma unroll
    for (int i = 0; i < 4; i++)
#pragma unroll
        for (int j = 0; j < 4; j++)
#pragma unroll
            for (int q = 0; q < 4; q++) acc[i][j][q] = 0.f;

    for (int kc = 0; kc < 32; kc++) {
        const int k0 = kc * 32;
#pragma unroll
        for (int h = 0; h < 2; h++) {
            int row = (tid >> 2) + h * 64;
            int g = tid & 3;
            uint32_t off = row * 64 + ((g ^ ((row >> 1) & 3)) << 4);
            size_t goA = (size_t)(m0 + row) * 1024 + k0 + g * 8;
            *(uint4*)((char*)sAH + off) = *(const uint4*)&g_topH[goA];
            *(uint4*)((char*)sAL + off) = *(const uint4*)&g_topL[goA];
            uint4 vh = make_uint4(0, 0, 0, 0), vl = make_uint4(0, 0, 0, 0);
            if (n0 + row < VOCAB) {
                size_t goB = (size_t)(n0 + row) * 1024 + k0 + g * 8;
                vh = *(const uint4*)&g_WoH[goB];
                vl = *(const uint4*)&g_WoL[goB];
            }
            *(uint4*)((char*)sBH + off) = vh;
            *(uint4*)((char*)sBL + off) = vl;
        }
        __syncthreads();
#pragma unroll
        for (int kb = 0; kb < 32; kb += 16) {
            uint32_t aH[4][4], aL[4][4], bH[4][2], bL[4][2];
            int ar = wm + (lane & 15);
            int ag = (kb >> 3) + (lane >> 4);
#pragma unroll
            for (int mf = 0; mf < 4; mf++) {
                int m = ar + mf * 16;
                uint32_t off = m * 64 + ((ag ^ ((m >> 1) & 3)) << 4);
                ldsm4(aH[mf], bAH + off);
                ldsm4(aL[mf], bAL + off);
            }
            int br = wn + (lane & 7);
            int bg = (kb >> 3) + ((lane >> 3) & 1);
#pragma unroll
            for (int nf = 0; nf < 4; nf++) {
                int n = br + nf * 8;
                uint32_t off = n * 64 + ((bg ^ ((n >> 1) & 3)) << 4);
                ldsm2(bH[nf], bBH + off);
                ldsm2(bL[nf], bBL + off);
            }
#pragma unroll
            for (int mf = 0; mf < 4; mf++)
#pragma unroll
                for (int nf = 0; nf < 4; nf++) {
                    mma16816(acc[mf][nf], aH[mf], bH[nf]);
                    mma16816(acc[mf][nf], aH[mf], bL[nf]);
                    mma16816(acc[mf][nf], aL[mf], bH[nf]);
                }
        }
        __syncthreads();
    }

    int r0 = m0 + wm + (lane >> 2);
    int c0 = n0 + wn + (lane & 3) * 2;
#pragma unroll
    for (int mf = 0; mf < 4; mf++)
#pragma unroll
        for (int nf = 0; nf < 4; nf++) {
            int r = r0 + mf * 16, c = c0 + nf * 8;
            if (c < VOCAB) {
                float bx = bout[c], by = bout[c + 1];
                *(float2*)&out[(size_t)r * VOCAB + c] =
                    make_float2(acc[mf][nf][0] + bx, acc[mf][nf][1] + by);
                *(float2*)&out[(size_t)(r + 8) * VOCAB + c] =
                    make_float2(acc[mf][nf][2] + bx, acc[mf][nf][3] + by);
            }
        }
}

// ---------------- final hidden state -----------------------------------
__global__ void k_final(float* __restrict__ out) {
    int idx = blockIdx.x * blockDim.x + threadIdx.x;
    if (idx < 2 * 64 * 1024) {
        int l = idx >> 16;
        int rem = idx & 65535;
        int b = rem >> 10, j = rem & 1023;
        out[(size_t)16384 * VOCAB + idx] = g_cat[b * 2048 + l * 1024 + j];
    }
}

// ---------------- launch ------------------------------------------------
extern "C" void kernel_launch(void* const* d_in, const int* in_sizes, int n_in,
                              void* d_out, int out_size) {
    const int*   inputs = (const int*)d_in[0];
    const float* hidden = (const float*)d_in[1];
    const float* Emb    = (const float*)d_in[2];
    const float* Wr0 = (const float*)d_in[3];  const float* br0 = (const float*)d_in[4];
    const float* Wz0 = (const float*)d_in[5];  const float* bz0 = (const float*)d_in[6];
    const float* Wh0 = (const float*)d_in[7];  const float* bh0 = (const float*)d_in[8];
    const float* Wr1 = (const float*)d_in[9];  const float* br1 = (const float*)d_in[10];
    const float* Wz1 = (const float*)d_in[11]; const float* bz1 = (const float*)d_in[12];
    const float* Wh1 = (const float*)d_in[13]; const float* bh1 = (const float*)d_in[14];
    const float* Wout = (const float*)d_in[15];
    const float* bout = (const float*)d_in[16];
    float* out = (float*)d_out;

    static bool attr_done = false;
    if (!attr_done) {
        cudaFuncSetAttribute(k_rec_persist, cudaFuncAttributeMaxDynamicSharedMemorySize, REC_SMEM);
        attr_done = true;
    }

    k_prep<<<512, 256>>>(hidden, br0, bz0, bh0, br1, bz1, bh1);
    k_wprep<<<dim3(96, 64, 5), 256>>>(Wr0, Wz0, Wh0, Wr1, Wz1, Wh1);
    k_esplit<<<20000, 256>>>(Emb);
    k_wsplit<<<dim3(313, 32), 256>>>(Wout);
    k_embed_mma<<<dim3(24, 128), 256>>>(inputs);
    k_rec_persist<<<148, 256, REC_SMEM>>>();
    k_logits_mma<<<dim3(79, 128), 256>>>(bout, out);
    k_final<<<512, 256>>>(out);
}

// round 16
// speedup vs baseline: 1.3009x; 1.3009x over previous
#include <cuda_runtime.h>
#include <cuda_bf16.h>
#include <stdint.h>
#include <math.h>

#define S_LEN 256
#define BATCH 64
#define VOCAB 10000
#define EDIM  512
#define HDIM  1024

typedef unsigned long long u64;

// ---------------- warp-level mma helpers --------------------------------
__device__ __forceinline__ uint32_t s2u(const void* p) {
    uint32_t a;
    asm("{ .reg .u64 t; cvta.to.shared.u64 t, %1; cvt.u32.u64 %0, t; }" : "=r"(a) : "l"(p));
    return a;
}
__device__ __forceinline__ void ldsm4(uint32_t* r, uint32_t addr) {
    asm volatile("ldmatrix.sync.aligned.m8n8.x4.shared.b16 {%0,%1,%2,%3}, [%4];"
        : "=r"(r[0]), "=r"(r[1]), "=r"(r[2]), "=r"(r[3]) : "r"(addr));
}
__device__ __forceinline__ void ldsm2(uint32_t* r, uint32_t addr) {
    asm volatile("ldmatrix.sync.aligned.m8n8.x2.shared.b16 {%0,%1}, [%2];"
        : "=r"(r[0]), "=r"(r[1]) : "r"(addr));
}
__device__ __forceinline__ void mma16816(float* d, const uint32_t* a, const uint32_t* b) {
    asm volatile(
        "mma.sync.aligned.m16n8k16.row.col.f32.bf16.bf16.f32 "
        "{%0,%1,%2,%3},{%4,%5,%6,%7},{%8,%9},{%0,%1,%2,%3};"
        : "+f"(d[0]), "+f"(d[1]), "+f"(d[2]), "+f"(d[3])
        : "r"(a[0]), "r"(a[1]), "r"(a[2]), "r"(a[3]), "r"(b[0]), "r"(b[1]));
}

// ---------------- scratch (static device memory) ------------------------
__device__ float g_bias[6 * 1024];
__device__ float g_xpre[(size_t)16384 * 3072];
__device__ float g_cat[64 * 2048];
__device__ float g_z[64 * 1024];
__device__ float g_xh1[64 * 1024];
__device__ float g_part[2359296];
__device__ int   g_cnt1[32] = {};
__device__ int   g_root = 0;
__device__ int   g_gen = 0;
// per-ntile generation counters (reset at kernel entry; target = splits*(s+1))
__device__ int   g_fA[16] = {};
__device__ int   g_fB[8]  = {};
__device__ int   g_fC[24] = {};
__device__ int   g_fD[8]  = {};
// bf16 hi/lo recurrent weights, [n][k] layout
__device__ __nv_bfloat16 g_W0An_H[(size_t)2048 * 1024], g_W0An_L[(size_t)2048 * 1024];
__device__ __nv_bfloat16 g_W0Bn_H[(size_t)1024 * 1024], g_W0Bn_L[(size_t)1024 * 1024];
__device__ __nv_bfloat16 g_W1An_H[(size_t)3072 * 2048], g_W1An_L[(size_t)3072 * 2048];
__device__ __nv_bfloat16 g_W1Bn_H[(size_t)1024 * 1024], g_W1Bn_L[(size_t)1024 * 1024];
// x-side weights [n][k] + embedding split
__device__ __nv_bfloat16 g_W0Xn_H[(size_t)3072 * 512], g_W0Xn_L[(size_t)3072 * 512];
__device__ __nv_bfloat16 g_EmbH[(size_t)10000 * 512], g_EmbL[(size_t)10000 * 512];
// bf16 hi/lo states
__device__ __nv_bfloat16 g_catH[64 * 2048], g_catL[64 * 2048];
__device__ __nv_bfloat16 g_rhH[64 * 1024], g_rhL[64 * 1024];
// bf16 split logits operands
__device__ __nv_bfloat16 g_topH[(size_t)16384 * 1024];
__device__ __nv_bfloat16 g_topL[(size_t)16384 * 1024];
__device__ __nv_bfloat16 g_WoH[(size_t)10000 * 1024];
__device__ __nv_bfloat16 g_WoL[(size_t)10000 * 1024];

// ---------------- two-level grid barrier -------------------------------
__device__ __forceinline__ void grid_bar(int &gen) {
    __syncthreads();
    if (threadIdx.x == 0) {
        __threadfence();
        int g = blockIdx.x >> 3;
        int ngrp = ((int)gridDim.x + 7) >> 3;
        int gsz = min(8, (int)gridDim.x - (g << 3));
        if (atomicAdd(&g_cnt1[g], 1) == gsz - 1) {
            atomicExch(&g_cnt1[g], 0);
            if (atomicAdd(&g_root, 1) == ngrp - 1) {
                atomicExch(&g_root, 0);
                __threadfence();
                atomicAdd(&g_gen, 1);
            }
        }
        volatile int* vg = &g_gen;
        while (*vg - gen <= 0) { }
        __threadfence();
    }
    gen++;
    __syncthreads();
}

// ---------------- per-ntile arrival sync (generation target) -----------
__device__ __forceinline__ void tile_sync(int* cnt, int target) {
    __syncthreads();
    if (threadIdx.x == 0) {
        __threadfence();
        atomicAdd(cnt, 1);
        volatile int* vc = cnt;
        while (*vc < target) { }
        __threadfence();
    }
    __syncthreads();
}

// ---------------- prep: bias + initial state ---------------------------
__global__ void k_prep(const float* __restrict__ hidden,
                       const float* __restrict__ br0, const float* __restrict__ bz0,
                       const float* __restrict__ bh0,
                       const float* __restrict__ br1, const float* __restrict__ bz1,
                       const float* __restrict__ bh1) {
    int i = blockIdx.x * blockDim.x + threadIdx.x;
    if (i < 1024) {
        g_bias[i]        = br0[i]; g_bias[1024 + i] = bz0[i]; g_bias[2048 + i] = bh0[i];
        g_bias[3072 + i] = br1[i]; g_bias[4096 + i] = bz1[i]; g_bias[5120 + i] = bh1[i];
    }
    if (i < 64 * 2048) {
        int b = i >> 11, j = i & 2047;
        float v = (j < 1024) ? hidden[b * 1024 + j]
                             : hidden[65536 + b * 1024 + (j - 1024)];
        g_cat[i] = v;
        __nv_bfloat16 hi = __float2bfloat16(v);
        g_catH[i] = hi;
        g_catL[i] = __float2bfloat16(v - __bfloat162float(hi));
    }
}

// ---------------- weight repack: [k][n] -> [n][k] bf16 hi/lo -----------
__global__ __launch_bounds__(256) void k_wprep(
    const float* __restrict__ Wr0, const float* __restrict__ Wz0, const float* __restrict__ Wh0,
    const float* __restrict__ Wr1, const float* __restrict__ Wz1, const float* __restrict__ Wh1) {
    __shared__ float t[32][33];
    const int which = blockIdx.z;
    const int Ns[5] = {2048, 1024, 3072, 1024, 3072};
    const int Ks[5] = {1024, 1024, 2048, 1024, 512};
    const int N = Ns[which], K = Ks[which];
    int n0 = blockIdx.x * 32, k0 = blockIdx.y * 32;
    if (n0 >= N || k0 >= K) return;
    int tx = threadIdx.x & 31, ty = threadIdx.x >> 5;
#pragma unroll
    for (int j = ty; j < 32; j += 8) {
        int k = k0 + j, n = n0 + tx;
        float v;
        if (which == 0)      v = (n < 1024) ? Wr0[(512 + k) * 1024 + n] : Wz0[(512 + k) * 1024 + n - 1024];
        else if (which == 1) v = Wh0[(512 + k) * 1024 + n];
        else if (which == 2) v = (n < 1024) ? Wr1[k * 1024 + n]
                               : (n < 2048) ? Wz1[k * 1024 + n - 1024]
                               : ((k < 1024) ? Wh1[k * 1024 + (n - 2048)] : 0.f);
        else if (which == 3) v = Wh1[(1024 + k) * 1024 + n];
        else                 v = (n < 1024) ? Wr0[k * 1024 + n]
                               : (n < 2048) ? Wz0[k * 1024 + n - 1024]
                               : Wh0[k * 1024 + n - 2048];
        t[j][tx] = v;
    }
    __syncthreads();
    __nv_bfloat16 *dH, *dL;
    if (which == 0)      { dH = g_W0An_H; dL = g_W0An_L; }
    else if (which == 1) { dH = g_W0Bn_H; dL = g_W0Bn_L; }
    else if (which == 2) { dH = g_W1An_H; dL = g_W1An_L; }
    else if (which == 3) { dH = g_W1Bn_H; dL = g_W1Bn_L; }
    else                 { dH = g_W0Xn_H; dL = g_W0Xn_L; }
#pragma unroll
    for (int j = ty; j < 32; j += 8) {
        int n = n0 + j, k = k0 + tx;
        float v = t[tx][j];
        __nv_bfloat16 hi = __float2bfloat16(v);
        dH[(size_t)n * K + k] = hi;
        dL[(size_t)n * K + k] = __float2bfloat16(v - __bfloat162float(hi));
    }
}

// ---------------- Emb split --------------------------------------------
__global__ __launch_bounds__(256) void k_esplit(const float* __restrict__ Emb) {
    size_t i = (size_t)blockIdx.x * 256 + threadIdx.x;
    if (i < (size_t)10000 * 512) {
        float v = Emb[i];
        __nv_bfloat16 hi = __float2bfloat16(v);
        g_EmbH[i] = hi;
        g_EmbL[i] = __float2bfloat16(v - __bfloat162float(hi));
    }
}

// ---------------- Wout split+transpose ---------------------------------
__global__ __launch_bounds__(256) void k_wsplit(const float* __restrict__ Wout) {
    __shared__ float t[32][33];
    int tx = threadIdx.x & 31, ty = threadIdx.x >> 5;
    int n0 = blockIdx.x * 32, k0 = blockIdx.y * 32;
#pragma unroll
    for (int j = ty; j < 32; j += 8) {
        float v = 0.f;
        if (n0 + tx < VOCAB) v = Wout[(size_t)(k0 + j) * VOCAB + n0 + tx];
        t[j][tx] = v;
    }
    __syncthreads();
#pragma unroll
    for (int j = ty; j < 32; j += 8) {
        int n = n0 + j;
        if (n < VOCAB) {
            float v = t[tx][j];
            __nv_bfloat16 hi = __float2bfloat16(v);
            g_WoH[(size_t)n * 1024 + k0 + tx] = hi;
            g_WoL[(size_t)n * 1024 + k0 + tx] = __float2bfloat16(v - __bfloat162float(hi));
        }
    }
}

// ---------------- embed GEMM via mma.sync ------------------------------
__global__ __launch_bounds__(256) void k_embed_mma(const int* __restrict__ inputs) {
    __shared__ __align__(16) __nv_bfloat16 sAH[128 * 32];
    __shared__ __align__(16) __nv_bfloat16 sAL[128 * 32];
    __shared__ __align__(16) __nv_bfloat16 sBH[128 * 32];
    __shared__ __align__(16) __nv_bfloat16 sBL[128 * 32];
    __shared__ int stok[128];
    const int tid = threadIdx.x, wid = tid >> 5, lane = tid & 31;
    const int m0 = blockIdx.y * 128, n0 = blockIdx.x * 128;
    const int wm = (wid & 1) * 64, wn = (wid >> 1) * 32;
    const uint32_t bAH = s2u(sAH), bAL = s2u(sAL), bBH = s2u(sBH), bBL = s2u(sBL);
    if (tid < 128) stok[tid] = inputs[m0 + tid];
    __syncthreads();

    float acc[4][4][4];
#pragma unroll
    for (int i = 0; i < 4; i++)
#pragma unroll
        for (int j = 0; j < 4; j++)
#pragma unroll
            for (int q = 0; q < 4; q++) acc[i][j][q] = 0.f;

    for (int kc = 0; kc < 16; kc++) {
        const int k0 = kc * 32;
#pragma unroll
        for (int h = 0; h < 2; h++) {
            int row = (tid >> 2) + h * 64;
            int g = tid & 3;
            uint32_t off = row * 64 + ((g ^ ((row >> 1) & 3)) << 4);
            size_t goA = (size_t)stok[row] * 512 + k0 + g * 8;
            *(uint4*)((char*)sAH + off) = *(const uint4*)&g_EmbH[goA];
            *(uint4*)((char*)sAL + off) = *(const uint4*)&g_EmbL[goA];
            size_t goB = (size_t)(n0 + row) * 512 + k0 + g * 8;
            *(uint4*)((char*)sBH + off) = *(const uint4*)&g_W0Xn_H[goB];
            *(uint4*)((char*)sBL + off) = *(const uint4*)&g_W0Xn_L[goB];
        }
        __syncthreads();
#pragma unroll
        for (int kb = 0; kb < 32; kb += 16) {
            uint32_t aH[4][4], aL[4][4], bH[4][2], bL[4][2];
            int ar = wm + (lane & 15);
            int ag = (kb >> 3) + (lane >> 4);
#pragma unroll
            for (int mf = 0; mf < 4; mf++) {
                int m = ar + mf * 16;
                uint32_t off = m * 64 + ((ag ^ ((m >> 1) & 3)) << 4);
                ldsm4(aH[mf], bAH + off);
                ldsm4(aL[mf], bAL + off);
            }
            int br = wn + (lane & 7);
            int bg = (kb >> 3) + ((lane >> 3) & 1);
#pragma unroll
            for (int nf = 0; nf < 4; nf++) {
                int n = br + nf * 8;
                uint32_t off = n * 64 + ((bg ^ ((n >> 1) & 3)) << 4);
                ldsm2(bH[nf], bBH + off);
                ldsm2(bL[nf], bBL + off);
            }
#pragma unroll
            for (int mf = 0; mf < 4; mf++)
#pragma unroll
                for (int nf = 0; nf < 4; nf++) {
                    mma16816(acc[mf][nf], aH[mf], bH[nf]);
                    mma16816(acc[mf][nf], aH[mf], bL[nf]);
                    mma16816(acc[mf][nf], aL[mf], bH[nf]);
                }
        }
        __syncthreads();
    }
    int r0 = m0 + wm + (lane >> 2);
    int c0 = n0 + wn + (lane & 3) * 2;
#pragma unroll
    for (int mf = 0; mf < 4; mf++)
#pragma unroll
        for (int nf = 0; nf < 4; nf++) {
            int r = r0 + mf * 16, c = c0 + nf * 8;
            *(float2*)&g_xpre[(size_t)r * 3072 + c] = make_float2(acc[mf][nf][0], acc[mf][nf][1]);
            *(float2*)&g_xpre[(size_t)(r + 8) * 3072 + c] = make_float2(acc[mf][nf][2], acc[mf][nf][3]);
        }
}

// ---------------- mma.sync split-K partial GEMM (recurrence) -----------
// CTA 64(M) x 128(N), BK=32; 8 warps = 2(m) x 4(n), warp tile 32x32.
__device__ __forceinline__ void phase_mma(
    const __nv_bfloat16* __restrict__ AH, const __nv_bfloat16* __restrict__ AL, int lda,
    const __nv_bfloat16* __restrict__ BH, const __nv_bfloat16* __restrict__ BL, int ldbk,
    int N, int ntile, int sp, int kbeg, int kend) {
    __shared__ __align__(16) __nv_bfloat16 sAH[64 * 32];
    __shared__ __align__(16) __nv_bfloat16 sAL[64 * 32];
    __shared__ __align__(16) __nv_bfloat16 sBH[128 * 32];
    __shared__ __align__(16) __nv_bfloat16 sBL[128 * 32];
    const int tid = threadIdx.x, wid = tid >> 5, lane = tid & 31;
    const int n0 = ntile * 128;
    const int wm = (wid & 1) * 32, wn = (wid >> 1) * 32;
    const uint32_t bAH = s2u(sAH), bAL = s2u(sAL), bBH = s2u(sBH), bBL = s2u(sBL);
    float acc[2][4][4];
#pragma unroll
    for (int i = 0; i < 2; i++)
#pragma unroll
        for (int j = 0; j < 4; j++)
#pragma unroll
            for (int q = 0; q < 4; q++) acc[i][j][q] = 0.f;

    const int arow = tid >> 2, ag4 = tid & 3;
    const uint32_t aoff = arow * 64 + ((ag4 ^ ((arow >> 1) & 3)) << 4);
    for (int k0 = kbeg; k0 < kend; k0 += 32) {
        *(uint4*)((char*)sAH + aoff) = __ldcg((const uint4*)(AH + (size_t)arow * lda + k0 + ag4 * 8));
        *(uint4*)((char*)sAL + aoff) = __ldcg((const uint4*)(AL + (size_t)arow * lda + k0 + ag4 * 8));
#pragma unroll
        for (int h = 0; h < 2; h++) {
            int row = arow + h * 64;
            uint32_t off = row * 64 + ((ag4 ^ ((row >> 1) & 3)) << 4);
            size_t go = (size_t)(n0 + row) * ldbk + k0 + ag4 * 8;
            *(uint4*)((char*)sBH + off) = *(const uint4*)(BH + go);
            *(uint4*)((char*)sBL + off) = *(const uint4*)(BL + go);
        }
        __syncthreads();
#pragma unroll
        for (int kb = 0; kb < 32; kb += 16) {
            uint32_t aH[2][4], aL[2][4], bH[4][2], bL[4][2];
            int ag = (kb >> 3) + (lane >> 4);
#pragma unroll
            for (int mf = 0; mf < 2; mf++) {
                int m = wm + (lane & 15) + mf * 16;
                uint32_t off = m * 64 + ((ag ^ ((m >> 1) & 3)) << 4);
                ldsm4(aH[mf], bAH + off);
                ldsm4(aL[mf], bAL + off);
            }
            int bg = (kb >> 3) + ((lane >> 3) & 1);
#pragma unroll
            for (int nf = 0; nf < 4; nf++) {
                int n = wn + (lane & 7) + nf * 8;
                uint32_t off = n * 64 + ((bg ^ ((n >> 1) & 3)) << 4);
                ldsm2(bH[nf], bBH + off);
                ldsm2(bL[nf], bBL + off);
            }
#pragma unroll
            for (int mf = 0; mf < 2; mf++)
#pragma unroll
                for (int nf = 0; nf < 4; nf++) {
                    mma16816(acc[mf][nf], aH[mf], bH[nf]);
                    mma16816(acc[mf][nf], aH[mf], bL[nf]);
                    mma16816(acc[mf][nf], aL[mf], bH[nf]);
                }
        }
        __syncthreads();
    }
    float* part = g_part + (size_t)sp * 64 * N;
    int r0 = wm + (lane >> 2), c0 = wn + (lane & 3) * 2;
#pragma unroll
    for (int mf = 0; mf < 2; mf++)
#pragma unroll
        for (int nf = 0; nf < 4; nf++) {
            int r = r0 + mf * 16, c = n0 + c0 + nf * 8;
            *(float2*)&part[(size_t)r * N + c]       = make_float2(acc[mf][nf][0], acc[mf][nf][1]);
            *(float2*)&part[(size_t)(r + 8) * N + c] = make_float2(acc[mf][nf][2], acc[mf][nf][3]);
        }
}

__device__ __forceinline__ float sigm(float x) { return 1.f / (1.f + expf(-x)); }
__device__ __forceinline__ void split4(const float* v, __nv_bfloat16* H, __nv_bfloat16* L, int idx) {
    __nv_bfloat162 h0, h1, l0, l1;
    __nv_bfloat16 a = __float2bfloat16(v[0]), b = __float2bfloat16(v[1]);
    __nv_bfloat16 c = __float2bfloat16(v[2]), d = __float2bfloat16(v[3]);
    h0.x = a; h0.y = b; h1.x = c; h1.y = d;
    l0.x = __float2bfloat16(v[0] - __bfloat162float(a));
    l0.y = __float2bfloat16(v[1] - __bfloat162float(b));
    l1.x = __float2bfloat16(v[2] - __bfloat162float(c));
    l1.y = __float2bfloat16(v[3] - __bfloat162float(d));
    *(__nv_bfloat162*)&H[idx] = h0; *(__nv_bfloat162*)&H[idx + 2] = h1;
    *(__nv_bfloat162*)&L[idx] = l0; *(__nv_bfloat162*)&L[idx + 2] = l1;
}

// ---------------- persistent recurrent kernel --------------------------
// Each phase: split-K GEMM -> per-ntile sync -> DISTRIBUTED fixup by that
// ntile's split-CTAs -> ONE global barrier. 4 global barriers/step.
// Counters are reset at kernel entry so every launch does identical work.
__global__ __launch_bounds__(256) void k_rec_persist() {
    const int cta = blockIdx.x, tid = threadIdx.x;
    int gen = *(volatile int*)&g_gen;

    // deterministic launch state: reset per-ntile counters, then barrier
    if (cta == 0 && tid < 64) {
        if (tid < 16)       g_fA[tid] = 0;
        else if (tid < 24)  g_fB[tid - 16] = 0;
        else if (tid < 48)  g_fC[tid - 24] = 0;
        else                g_fD[tid - 48] = 0;
    }
    grid_bar(gen);

    for (int s = 0; s < S_LEN; s++) {
        const int sb = s * BATCH;
        // ---- G1: h0 @ W0A  (16 nt x 8 sp, K128) ----
        if (cta < 128) {
            int nt = cta & 15, sp = cta >> 4;
            phase_mma(g_catH, g_catL, 2048, g_W0An_H, g_W0An_L, 1024,
                      2048, nt, sp, sp * 128, sp * 128 + 128);
            tile_sync(&g_fA[nt], 8 * (s + 1));
            int n0 = nt * 128;
            int local = sp * 256 + tid;   // 0..2047, one float4 slot each
            {
                int r = local >> 5, n = n0 + (local & 31) * 4;
                int e = r * 2048 + n;
                float4 s4 = make_float4(0.f, 0.f, 0.f, 0.f);
#pragma unroll
                for (int p = 0; p < 8; p++) {
                    float4 v = __ldcg((const float4*)&g_part[p * 131072 + e]);
                    s4.x += v.x; s4.y += v.y; s4.z += v.z; s4.w += v.w;
                }
                float4 xp = *(const float4*)&g_xpre[(size_t)(sb + r) * 3072 + n];
                float4 bi = *(const float4*)&g_bias[n];
                float pre[4] = { s4.x + xp.x + bi.x, s4.y + xp.y + bi.y,
                                 s4.z + xp.z + bi.z, s4.w + xp.w + bi.w };
                if (n < 1024) {
                    float4 cc = __ldcg((const float4*)&g_cat[r * 2048 + n]);
                    float rh[4] = { sigm(pre[0]) * cc.x, sigm(pre[1]) * cc.y,
                                    sigm(pre[2]) * cc.z, sigm(pre[3]) * cc.w };
                    split4(rh, g_rhH, g_rhL, r * 1024 + n);
                } else {
                    int j = n - 1024;
                    *(float4*)&g_z[r * 1024 + j] =
                        make_float4(sigm(pre[0]), sigm(pre[1]), sigm(pre[2]), sigm(pre[3]));
                }
            }
        }
        grid_bar(gen);
        // ---- G2: rh0 @ W0B  (8 nt x 8 sp, K128) ----
        if (cta < 64) {
            int nt = cta & 7, sp = cta >> 3;
            phase_mma(g_rhH, g_rhL, 1024, g_W0Bn_H, g_W0Bn_L, 1024,
                      1024, nt, sp, sp * 128, sp * 128 + 128);
            tile_sync(&g_fB[nt], 8 * (s + 1));
            int n0 = nt * 128;
            int local = sp * 256 + tid;
            {
                int r = local >> 5, n = n0 + (local & 31) * 4;
                int e = r * 1024 + n;
                float4 s4 = make_float4(0.f, 0.f, 0.f, 0.f);
#pragma unroll
                for (int p = 0; p < 8; p++) {
                    float4 v = __ldcg((const float4*)&g_part[p * 65536 + e]);
                    s4.x += v.x; s4.y += v.y; s4.z += v.z; s4.w += v.w;
                }
                float4 xp = *(const float4*)&g_xpre[(size_t)(sb + r) * 3072 + 2048 + n];
                float4 bi = *(const float4*)&g_bias[2048 + n];
                float4 z4 = __ldcg((const float4*)&g_z[e]);
                float4 h4 = __ldcg((const float4*)&g_cat[r * 2048 + n]);
                float hn[4];
                hn[0] = (1.f - z4.x) * h4.x + z4.x * tanhf(s4.x + xp.x + bi.x);
                hn[1] = (1.f - z4.y) * h4.y + z4.y * tanhf(s4.y + xp.y + bi.y);
                hn[2] = (1.f - z4.z) * h4.z + z4.z * tanhf(s4.z + xp.z + bi.z);
                hn[3] = (1.f - z4.w) * h4.w + z4.w * tanhf(s4.w + xp.w + bi.w);
                *(float4*)&g_cat[r * 2048 + n] = make_float4(hn[0], hn[1], hn[2], hn[3]);
                split4(hn, g_catH, g_catL, r * 2048 + n);
            }
        }
        grid_bar(gen);
        // ---- G3: [h0new|h1] @ W1A  (24 nt x 6 sp, K352) ----
        if (cta < 144) {
            int nt = cta % 24, sp = cta / 24;
            int kb = sp * 352, ke = min(2048, kb + 352);
            phase_mma(g_catH, g_catL, 2048, g_W1An_H, g_W1An_L, 2048,
                      3072, nt, sp, kb, ke);
            tile_sync(&g_fC[nt], 6 * (s + 1));
            int n0 = nt * 128;
            for (int local = sp * 256 + tid; local < 2048; local += 1536) {
                int r = local >> 5, n = n0 + (local & 31) * 4;
                int e = r * 3072 + n;
                float4 s4 = make_float4(0.f, 0.f, 0.f, 0.f);
#pragma unroll
                for (int p = 0; p < 6; p++) {
                    float4 v = __ldcg((const float4*)&g_part[p * 196608 + e]);
                    s4.x += v.x; s4.y += v.y; s4.z += v.z; s4.w += v.w;
                }
                if (n < 1024) {
                    float4 bi = *(const float4*)&g_bias[3072 + n];
                    float4 cc = __ldcg((const float4*)&g_cat[r * 2048 + 1024 + n]);
                    float rh[4] = { sigm(s4.x + bi.x) * cc.x, sigm(s4.y + bi.y) * cc.y,
                                    sigm(s4.z + bi.z) * cc.z, sigm(s4.w + bi.w) * cc.w };
                    split4(rh, g_rhH, g_rhL, r * 1024 + n);
                } else if (n < 2048) {
                    int j = n - 1024;
                    float4 bi = *(const float4*)&g_bias[4096 + j];
                    *(float4*)&g_z[r * 1024 + j] = make_float4(
                        sigm(s4.x + bi.x), sigm(s4.y + bi.y), sigm(s4.z + bi.z), sigm(s4.w + bi.w));
                } else {
                    *(float4*)&g_xh1[r * 1024 + n - 2048] = s4;
                }
            }
        }
        grid_bar(gen);
        // ---- G4: rh1 @ W1B  (8 nt x 8 sp, K128) ----
        if (cta < 64) {
            int nt = cta & 7, sp = cta >> 3;
            phase_mma(g_rhH, g_rhL, 1024, g_W1Bn_H, g_W1Bn_L, 1024,
                      1024, nt, sp, sp * 128, sp * 128 + 128);
            tile_sync(&g_fD[nt], 8 * (s + 1));
            int n0 = nt * 128;
            int local = sp * 256 + tid;
            {
                int r = local >> 5, n = n0 + (local & 31) * 4;
                int e = r * 1024 + n;
                float4 s4 = make_float4(0.f, 0.f, 0.f, 0.f);
#pragma unroll
                for (int p = 0; p < 8; p++) {
                    float4 v = __ldcg((const float4*)&g_part[p * 65536 + e]);
                    s4.x += v.x; s4.y += v.y; s4.z += v.z; s4.w += v.w;
                }
                float4 xh = __ldcg((const float4*)&g_xh1[e]);
                float4 bi = *(const float4*)&g_bias[5120 + n];
                float4 z4 = __ldcg((const float4*)&g_z[e]);
                float4 h4 = __ldcg((const float4*)&g_cat[r * 2048 + 1024 + n]);
                float hn[4];
                hn[0] = (1.f - z4.x) * h4.x + z4.x * tanhf(s4.x + xh.x + bi.x);
                hn[1] = (1.f - z4.y) * h4.y + z4.y * tanhf(s4.y + xh.y + bi.y);
                hn[2] = (1.f - z4.z) * h4.z + z4.z * tanhf(s4.z + xh.z + bi.z);
                hn[3] = (1.f - z4.w) * h4.w + z4.w * tanhf(s4.w + xh.w + bi.w);
                *(float4*)&g_cat[r * 2048 + 1024 + n] = make_float4(hn[0], hn[1], hn[2], hn[3]);
                split4(hn, g_catH, g_catL, r * 2048 + 1024 + n);
                split4(hn, g_topH, g_topL, (int)((size_t)(sb + r) * 1024 + n));
            }
        }
        grid_bar(gen);
    }
}

// ---------------- logits GEMM via mma.sync (hi/lo, 3-pass) -------------
__global__ __launch_bounds__(256) void k_logits_mma(const float* __restrict__ bout,
                                                    float* __restrict__ out) {
    __shared__ __align__(16) __nv_bfloat16 sAH[128 * 32];
    __shared__ __align__(16) __nv_bfloat16 sAL[128 * 32];
    __shared__ __align__(16) __nv_bfloat16 sBH[128 * 32];
    __shared__ __align__(16) __nv_bfloat16 sBL[128 * 32];
    const int tid = threadIdx.x, wid = tid >> 5, lane = tid & 31;
    const int m0 = blockIdx.y * 128, n0 = blockIdx.x * 128;
    const int wm = (wid & 1) * 64, wn = (wid >> 1) * 32;
    const uint32_t bAH = s2u(sAH), bAL = s2u(sAL), bBH = s2u(sBH), bBL = s2u(sBL);

    float acc[4][4][4];
#pragma unroll
    for (int i = 0; i < 4; i++)
#pragma unroll
        for (int j = 0; j < 4; j++)
#pragma unroll
            for (int q = 0; q < 4; q++) acc[i][j][q] = 0.f;

    for (int kc = 0; kc < 32; kc++) {
        const int k0 = kc * 32;
#pragma unroll
        for (int h = 0; h < 2; h++) {
            int row = (tid >> 2) + h * 64;
            int g = tid & 3;
            uint32_t off = row * 64 + ((g ^ ((row >> 1) & 3)) << 4);
            size_t goA = (size_t)(m0 + row) * 1024 + k0 + g * 8;
            *(uint4*)((char*)sAH + off) = *(const uint4*)&g_topH[goA];
            *(uint4*)((char*)sAL + off) = *(const uint4*)&g_topL[goA];
            uint4 vh = make_uint4(0, 0, 0, 0), vl = make_uint4(0, 0, 0, 0);
            if (n0 + row < VOCAB) {
                size_t goB = (size_t)(n0 + row) * 1024 + k0 + g * 8;
                vh = *(const uint4*)&g_WoH[goB];
                vl = *(const uint4*)&g_WoL[goB];
            }
            *(uint4*)((char*)sBH + off) = vh;
            *(uint4*)((char*)sBL + off) = vl;
        }
        __syncthreads();
#pragma unroll
        for (int kb = 0; kb < 32; kb += 16) {
            uint32_t aH[4][4], aL[4][4], bH[4][2], bL[4][2];
            int ar = wm + (lane & 15);
            int ag = (kb >> 3) + (lane >> 4);
#pragma unroll
            for (int mf = 0; mf < 4; mf++) {
                int m = ar + mf * 16;
                uint32_t off = m * 64 + ((ag ^ ((m >> 1) & 3)) << 4);
                ldsm4(aH[mf], bAH + off);
                ldsm4(aL[mf], bAL + off);
            }
            int br = wn + (lane & 7);
            int bg = (kb >> 3) + ((lane >> 3) & 1);
#pragma unroll
            for (int nf = 0; nf < 4; nf++) {
                int n = br + nf * 8;
                uint32_t off = n * 64 + ((bg ^ ((n >> 1) & 3)) << 4);
                ldsm2(bH[nf], bBH + off);
                ldsm2(bL[nf], bBL + off);
            }
#pragma unroll
            for (int mf = 0; mf < 4; mf++)
#pragma unroll
                for (int nf = 0; nf < 4; nf++) {
                    mma16816(acc[mf][nf], aH[mf], bH[nf]);
                    mma16816(acc[mf][nf], aH[mf], bL[nf]);
                    mma16816(acc[mf][nf], aL[mf], bH[nf]);
                }
        }
        __syncthreads();
    }

    int r0 = m0 + wm + (lane >> 2);
    int c0 = n0 + wn + (lane & 3) * 2;
#pragma unroll
    for (int mf = 0; mf < 4; mf++)
#pragma unroll
        for (int nf = 0; nf < 4; nf++) {
            int r = r0 + mf * 16, c = c0 + nf * 8;
            if (c < VOCAB) {
                float bx = bout[c], by = bout[c + 1];
                *(float2*)&out[(size_t)r * VOCAB + c] =
                    make_float2(acc[mf][nf][0] + bx, acc[mf][nf][1] + by);
                *(float2*)&out[(size_t)(r + 8) * VOCAB + c] =
                    make_float2(acc[mf][nf][2] + bx, acc[mf][nf][3] + by);
            }
        }
}

// ---------------- final hidden state -----------------------------------
__global__ void k_final(float* __restrict__ out) {
    int idx = blockIdx.x * blockDim.x + threadIdx.x;
    if (idx < 2 * 64 * 1024) {
        int l = idx >> 16;
        int rem = idx & 65535;
        int b = rem >> 10, j = rem & 1023;
        out[(size_t)16384 * VOCAB + idx] = g_cat[b * 2048 + l * 1024 + j];
    }
}

// ---------------- launch ------------------------------------------------
extern "C" void kernel_launch(void* const* d_in, const int* in_sizes, int n_in,
                              void* d_out, int out_size) {
    const int*   inputs = (const int*)d_in[0];
    const float* hidden = (const float*)d_in[1];
    const float* Emb    = (const float*)d_in[2];
    const float* Wr0 = (const float*)d_in[3];  const float* br0 = (const float*)d_in[4];
    const float* Wz0 = (const float*)d_in[5];  const float* bz0 = (const float*)d_in[6];
    const float* Wh0 = (const float*)d_in[7];  const float* bh0 = (const float*)d_in[8];
    const float* Wr1 = (const float*)d_in[9];  const float* br1 = (const float*)d_in[10];
    const float* Wz1 = (const float*)d_in[11]; const float* bz1 = (const float*)d_in[12];
    const float* Wh1 = (const float*)d_in[13]; const float* bh1 = (const float*)d_in[14];
    const float* Wout = (const float*)d_in[15];
    const float* bout = (const float*)d_in[16];
    float* out = (float*)d_out;

    k_prep<<<512, 256>>>(hidden, br0, bz0, bh0, br1, bz1, bh1);
    k_wprep<<<dim3(96, 64, 5), 256>>>(Wr0, Wz0, Wh0, Wr1, Wz1, Wh1);
    k_esplit<<<20000, 256>>>(Emb);
    k_wsplit<<<dim3(313, 32), 256>>>(Wout);
    k_embed_mma<<<dim3(24, 128), 256>>>(inputs);
    k_rec_persist<<<148, 256>>>();
    k_logits_mma<<<dim3(79, 128), 256>>>(bout, out);
    k_final<<<512, 256>>>(out);
}